// round 1
// baseline (speedup 1.0000x reference)
#include <cuda_runtime.h>
#include <cstdint>

#define B_TOT   65536
#define DIM_S   64
#define NEXP    8
#define HID     256
#define BM      64
#define KT      32
#define NTHR    256

// SMEM layout (floats):
//  s_x  : 64 x 68   (st tile, padded)         [0      .. 4352)
//  s_h  : 64 x 260  (h1, padded)              [4352   .. 20992)
//  s_w  : 2 x 32 x 256 (double-buffer W tile) [20992  .. 37376)
//  s_w3 : 256                                 [37376  .. 37632)
#define OFF_X   0
#define OFF_H   4352
#define OFF_W   20992
#define OFF_W3  37376
#define SMEM_FLOATS 37632
#define LDA_X   68
#define LDA_H   260

__device__ __forceinline__ void cp_async16(uint32_t saddr, const void* gptr) {
    asm volatile("cp.async.cg.shared.global [%0], [%1], 16;\n"
                 :: "r"(saddr), "l"(gptr));
}
__device__ __forceinline__ void cp_commit() {
    asm volatile("cp.async.commit_group;\n");
}
template <int N>
__device__ __forceinline__ void cp_wait() {
    asm volatile("cp.async.wait_group %0;\n" :: "n"(N));
}

// GEMM: acc[4][16] += sA(64 x K, stride lda) * gW(K x 256), K = ktiles*32.
// Weight tiles streamed global->smem via double-buffered cp.async.
__device__ __forceinline__ void gemm_tiles(
    const float* __restrict__ gW, int ktiles,
    const float* __restrict__ sA, int lda,
    float* __restrict__ s_w,
    float acc[4][16], int tid, int tm, int tn)
{
    // prefetch tile 0 into buffer 0
    {
        uint32_t sbase = (uint32_t)__cvta_generic_to_shared(s_w);
        #pragma unroll
        for (int t = 0; t < 8; t++) {
            int idx = tid + t * NTHR;                 // 0..2047 float4s
            cp_async16(sbase + idx * 16, gW + idx * 4);
        }
        cp_commit();
    }

    for (int kt = 0; kt < ktiles; kt++) {
        const float* wcur = s_w + (kt & 1) * (KT * HID);
        if (kt + 1 < ktiles) {
            float* wnxt = s_w + ((kt + 1) & 1) * (KT * HID);
            uint32_t sbase = (uint32_t)__cvta_generic_to_shared(wnxt);
            const float* g = gW + (size_t)(kt + 1) * KT * HID;
            #pragma unroll
            for (int t = 0; t < 8; t++) {
                int idx = tid + t * NTHR;
                cp_async16(sbase + idx * 16, g + idx * 4);
            }
            cp_commit();
            cp_wait<1>();          // tile kt's group has landed
        } else {
            cp_wait<0>();
        }
        __syncthreads();

        const float* a0 = sA + (tm * 4) * lda + kt * KT;
        #pragma unroll
        for (int kk = 0; kk < KT; kk++) {
            float a[4];
            #pragma unroll
            for (int i = 0; i < 4; i++) a[i] = a0[i * lda + kk];
            const float* wr = wcur + kk * HID + tn * 16;
            float4 b0 = *(const float4*)(wr + 0);
            float4 b1 = *(const float4*)(wr + 4);
            float4 b2 = *(const float4*)(wr + 8);
            float4 b3 = *(const float4*)(wr + 12);
            #pragma unroll
            for (int i = 0; i < 4; i++) {
                acc[i][0]  += a[i] * b0.x;  acc[i][1]  += a[i] * b0.y;
                acc[i][2]  += a[i] * b0.z;  acc[i][3]  += a[i] * b0.w;
                acc[i][4]  += a[i] * b1.x;  acc[i][5]  += a[i] * b1.y;
                acc[i][6]  += a[i] * b1.z;  acc[i][7]  += a[i] * b1.w;
                acc[i][8]  += a[i] * b2.x;  acc[i][9]  += a[i] * b2.y;
                acc[i][10] += a[i] * b2.z;  acc[i][11] += a[i] * b2.w;
                acc[i][12] += a[i] * b3.x;  acc[i][13] += a[i] * b3.y;
                acc[i][14] += a[i] * b3.z;  acc[i][15] += a[i] * b3.w;
            }
        }
        __syncthreads();   // protect buffer reuse by next iteration's prefetch
    }
}

__global__ void __launch_bounds__(NTHR, 1)
moe_disc_kernel(const float* __restrict__ st,
                const float* __restrict__ W1, const float* __restrict__ b1,
                const float* __restrict__ W2, const float* __restrict__ b2,
                const float* __restrict__ W3, const float* __restrict__ b3,
                float* __restrict__ out)
{
    extern __shared__ float smem[];
    float* s_x  = smem + OFF_X;
    float* s_h  = smem + OFF_H;
    float* s_w  = smem + OFF_W;
    float* s_w3 = smem + OFF_W3;

    const int tid = threadIdx.x;
    const int c   = blockIdx.y;
    const int m0  = blockIdx.x * BM;
    const int tm  = tid >> 4;    // 0..15 -> rows tm*4..tm*4+3
    const int tn  = tid & 15;    // 0..15 -> cols tn*16..tn*16+15

    const float* W1c = W1 + (size_t)c * DIM_S * HID;
    const float* W2c = W2 + (size_t)c * HID * HID;
    const float* b1c = b1 + c * HID;
    const float* b2c = b2 + c * HID;
    const float* w3c = W3 + c * HID;

    // load st tile [64 x 64] (padded stride 68) and w3 into smem
    #pragma unroll
    for (int t = 0; t < 4; t++) {
        int idx = tid + t * NTHR;          // 0..1023 float4s
        int r = idx >> 4, c4 = idx & 15;
        float4 v = *reinterpret_cast<const float4*>(
            st + (size_t)(m0 + r) * DIM_S + c4 * 4);
        *reinterpret_cast<float4*>(s_x + r * LDA_X + c4 * 4) = v;
    }
    s_w3[tid] = w3c[tid];

    // ---------- layer 1: h1 = relu(st @ W1c + b1c) ----------
    float acc[4][16];
    #pragma unroll
    for (int i = 0; i < 4; i++)
        #pragma unroll
        for (int j = 0; j < 16; j++) acc[i][j] = 0.f;

    // gemm's first internal __syncthreads orders the s_x/s_w3 stores above
    gemm_tiles(W1c, DIM_S / KT, s_x, LDA_X, s_w, acc, tid, tm, tn);

    #pragma unroll
    for (int i = 0; i < 4; i++) {
        int m = tm * 4 + i;
        #pragma unroll
        for (int q = 0; q < 4; q++) {
            int n = tn * 16 + q * 4;
            float4 bb = *(const float4*)(b1c + n);
            float4 v;
            v.x = fmaxf(acc[i][q * 4 + 0] + bb.x, 0.f);
            v.y = fmaxf(acc[i][q * 4 + 1] + bb.y, 0.f);
            v.z = fmaxf(acc[i][q * 4 + 2] + bb.z, 0.f);
            v.w = fmaxf(acc[i][q * 4 + 3] + bb.w, 0.f);
            *(float4*)(s_h + m * LDA_H + n) = v;
        }
    }

    // ---------- layer 2: h2 = relu(h1 @ W2c + b2c) (acc in regs) ----------
    #pragma unroll
    for (int i = 0; i < 4; i++)
        #pragma unroll
        for (int j = 0; j < 16; j++) acc[i][j] = 0.f;

    // gemm's first internal __syncthreads orders the s_h stores above
    gemm_tiles(W2c, HID / KT, s_h, LDA_H, s_w, acc, tid, tm, tn);

    // ---------- layer 3 fused epilogue: d = h2 @ w3 + b3 ----------
    float part[4] = {0.f, 0.f, 0.f, 0.f};
    #pragma unroll
    for (int q = 0; q < 4; q++) {
        int n = tn * 16 + q * 4;
        float4 bb = *(const float4*)(b2c + n);
        float4 ww = *(const float4*)(s_w3 + n);
        #pragma unroll
        for (int i = 0; i < 4; i++) {
            part[i] += fmaxf(acc[i][q * 4 + 0] + bb.x, 0.f) * ww.x
                     + fmaxf(acc[i][q * 4 + 1] + bb.y, 0.f) * ww.y
                     + fmaxf(acc[i][q * 4 + 2] + bb.z, 0.f) * ww.z
                     + fmaxf(acc[i][q * 4 + 3] + bb.w, 0.f) * ww.w;
        }
    }
    // reduce across the 16 tn lanes (tid = tm*16+tn -> lane = (tm&1)*16 + tn)
    #pragma unroll
    for (int off = 8; off >= 1; off >>= 1) {
        #pragma unroll
        for (int i = 0; i < 4; i++)
            part[i] += __shfl_down_sync(0xFFFFFFFFu, part[i], off, 16);
    }
    if (tn == 0) {
        float bias3 = b3[c];
        #pragma unroll
        for (int i = 0; i < 4; i++)
            out[(size_t)(m0 + tm * 4 + i) * NEXP + c] = part[i] + bias3;
    }
}

extern "C" void kernel_launch(void* const* d_in, const int* in_sizes, int n_in,
                              void* d_out, int out_size)
{
    const float* st = (const float*)d_in[0];
    const float* W1 = (const float*)d_in[1];
    const float* b1 = (const float*)d_in[2];
    const float* W2 = (const float*)d_in[3];
    const float* b2 = (const float*)d_in[4];
    const float* W3 = (const float*)d_in[5];
    const float* b3 = (const float*)d_in[6];
    float* out = (float*)d_out;

    const int smem_bytes = SMEM_FLOATS * (int)sizeof(float);   // 150528
    cudaFuncSetAttribute(moe_disc_kernel,
                         cudaFuncAttributeMaxDynamicSharedMemorySize, smem_bytes);

    dim3 grid(B_TOT / BM, NEXP);
    moe_disc_kernel<<<grid, NTHR, smem_bytes>>>(st, W1, b1, W2, b2, W3, b3, out);
}

// round 3
// speedup vs baseline: 4.3497x; 4.3497x over previous
#include <cuda_runtime.h>
#include <cstdint>

#define NEXP   8
#define DIM_S  64
#define HID    256
#define BM     64
#define NTHR   256

// ---- SMEM layout in floats ----
// AF : A-fragments. layer1: [mt4][ks8][lane32][4]  (4096 floats)
//                   layer2: [mt4][ks32][lane32][4] (16384 floats)
#define OFF_AF    0
#define WBLK      65                 // padded W-frag block stride (words)
#define WBUF_FL   (256 * WBLK)       // 256 blocks per chunk = 16640 floats
#define OFF_WB0   16384
#define OFF_WB1   (OFF_WB0 + WBUF_FL)          // 33024
#define OFF_B1    (OFF_WB1 + WBUF_FL)          // 49664
#define OFF_B2    (OFF_B1 + 256)
#define OFF_W3    (OFF_B2 + 256)
#define OFF_PART  (OFF_W3 + 256)               // 64 rows x 8 warps
#define SMEM_FLOATS (OFF_PART + 512)           // 50944 floats = 203776 B

__device__ __forceinline__ uint32_t f2tf32(float f) {
    uint32_t u; asm("cvt.rna.tf32.f32 %0, %1;" : "=r"(u) : "f"(f)); return u;
}
__device__ __forceinline__ float tf32f(float f) {
    return __uint_as_float(f2tf32(f));
}

__device__ __forceinline__ void mma_tf32(float c[4], const uint32_t a[4],
                                         uint32_t b0, uint32_t b1) {
    asm volatile(
        "mma.sync.aligned.m16n8k8.row.col.f32.tf32.tf32.f32 "
        "{%0,%1,%2,%3}, {%4,%5,%6,%7}, {%8,%9}, {%0,%1,%2,%3};"
        : "+f"(c[0]), "+f"(c[1]), "+f"(c[2]), "+f"(c[3])
        : "r"(a[0]), "r"(a[1]), "r"(a[2]), "r"(a[3]), "r"(b0), "r"(b1));
}

// Stage one [64k x 256n] weight slice (row-major, ld=HID) into mma B-fragment
// layout: blk = (n>>3)*8 + ks, word = blk*WBLK + reg*32 + lane,
// lane = (k&3) + (n&7)*4, reg = (k&7)>>2.  tf32-rounded.
__device__ __forceinline__ void stage_w_frags(const float* __restrict__ g,
                                              float* __restrict__ buf, int tid) {
    #pragma unroll
    for (int i = 0; i < 16; i++) {
        int idx = tid + i * NTHR;        // 0..4095 float4
        int k  = idx >> 6;               // 0..63
        int nf = idx & 63;
        float4 v = *reinterpret_cast<const float4*>(g + (size_t)k * HID + nf * 4);
        int ks  = k >> 3;
        int reg = (k & 7) >> 2;
        int lb  = k & 3;
        float vv[4] = {v.x, v.y, v.z, v.w};
        #pragma unroll
        for (int j = 0; j < 4; j++) {
            int n = nf * 4 + j;
            int blk = (n >> 3) * 8 + ks;
            int lane = lb + (n & 7) * 4;
            buf[blk * WBLK + reg * 32 + lane] = tf32f(vv[j]);
        }
    }
}

// One K=64 chunk: acc[mt][nt][4] += A(64x64 frags) * B(chunk frags, this warp's
// 32-col slice). af: fragment base, totks = ksteps in A layout, ks0 = chunk base.
__device__ __forceinline__ void gemm_chunk(const float* __restrict__ af, int totks, int ks0,
                                           const float* __restrict__ wf,
                                           float acc[4][4][4], int lane) {
    #pragma unroll
    for (int ks = 0; ks < 8; ks++) {
        uint32_t a[4][4];
        #pragma unroll
        for (int mt = 0; mt < 4; mt++) {
            float4 av = *reinterpret_cast<const float4*>(
                af + ((size_t)((mt * totks) + ks0 + ks) * 32 + lane) * 4);
            a[mt][0] = __float_as_uint(av.x); a[mt][1] = __float_as_uint(av.y);
            a[mt][2] = __float_as_uint(av.z); a[mt][3] = __float_as_uint(av.w);
        }
        #pragma unroll
        for (int nt = 0; nt < 4; nt++) {
            const float* bb = wf + (nt * 8 + ks) * WBLK;
            uint32_t b0 = __float_as_uint(bb[lane]);
            uint32_t b1 = __float_as_uint(bb[32 + lane]);
            #pragma unroll
            for (int mt = 0; mt < 4; mt++)
                mma_tf32(acc[mt][nt], a[mt], b0, b1);
        }
    }
}

__global__ void __launch_bounds__(NTHR, 1)
moe_disc_mma(const float* __restrict__ st,
             const float* __restrict__ W1, const float* __restrict__ b1,
             const float* __restrict__ W2, const float* __restrict__ b2,
             const float* __restrict__ W3, const float* __restrict__ b3,
             float* __restrict__ out)
{
    extern __shared__ float sm[];
    const int tid  = threadIdx.x;
    const int wid  = tid >> 5;
    const int lane = tid & 31;
    const int c    = blockIdx.y;
    const int m0   = blockIdx.x * BM;

    const float* W1c = W1 + (size_t)c * DIM_S * HID;
    const float* W2c = W2 + (size_t)c * HID * HID;

    // biases / w3
    sm[OFF_B1 + tid] = b1[c * HID + tid];
    sm[OFF_B2 + tid] = b2[c * HID + tid];
    sm[OFF_W3 + tid] = W3[c * HID + tid];

    // ---- stage layer1 A-fragments (st tile, totks = 8) ----
    #pragma unroll
    for (int i = 0; i < 4; i++) {
        int idx = tid + i * NTHR;        // 0..1023 float4
        int row = idx >> 4;
        int cf  = idx & 15;
        float4 v = *reinterpret_cast<const float4*>(
            st + (size_t)(m0 + row) * DIM_S + cf * 4);
        int mt = row >> 4, r = row & 15;
        float vv[4] = {v.x, v.y, v.z, v.w};
        #pragma unroll
        for (int j = 0; j < 4; j++) {
            int col = cf * 4 + j;
            int ks = col >> 3, kc = col & 7;
            int l2 = (r & 7) * 4 + (kc & 3);
            int r2 = 2 * (kc >> 2) + (r >> 3);
            sm[OFF_AF + ((size_t)(mt * 8 + ks) * 32 + l2) * 4 + r2] = tf32f(vv[j]);
        }
    }
    // stage W1 fragments
    stage_w_frags(W1c, sm + OFF_WB0, tid);
    __syncthreads();

    // stage W2 chunk 0 into WB1 (overlaps layer1 compute across warps)
    stage_w_frags(W2c, sm + OFF_WB1, tid);

    // ---- layer 1 GEMM ----
    float acc[4][4][4];
    #pragma unroll
    for (int a = 0; a < 4; a++)
        #pragma unroll
        for (int b = 0; b < 4; b++)
            #pragma unroll
            for (int d = 0; d < 4; d++) acc[a][b][d] = 0.f;

    gemm_chunk(sm + OFF_AF, 8, 0, sm + OFF_WB0 + wid * (32 * WBLK), acc, lane);
    __syncthreads();   // everyone done reading AF(layer1) + WB0

    // ---- epilogue 1: h1 = tf32(relu(acc + b1)) -> AF (totks = 32) ----
    {
        const int n0 = wid * 32;
        #pragma unroll
        for (int mt = 0; mt < 4; mt++)
            #pragma unroll
            for (int nt = 0; nt < 4; nt++)
                #pragma unroll
                for (int reg = 0; reg < 4; reg++) {
                    int col = n0 + nt * 8 + 2 * (lane & 3) + (reg & 1);
                    int row = mt * 16 + (lane >> 2) + 8 * (reg >> 1);
                    float f = fmaxf(acc[mt][nt][reg] + sm[OFF_B1 + col], 0.f);
                    int ks = col >> 3, kc = col & 7;
                    int l2 = (row & 7) * 4 + (kc & 3);
                    int r2 = 2 * (kc >> 2) + ((row & 15) >> 3);
                    sm[OFF_AF + ((size_t)(mt * 32 + ks) * 32 + l2) * 4 + r2] = tf32f(f);
                }
    }
    // reset acc for layer 2
    #pragma unroll
    for (int a = 0; a < 4; a++)
        #pragma unroll
        for (int b = 0; b < 4; b++)
            #pragma unroll
            for (int d = 0; d < 4; d++) acc[a][b][d] = 0.f;

    // stage W2 chunk 1 into WB0 (free after sync above)
    stage_w_frags(W2c + 1 * 64 * HID, sm + OFF_WB0, tid);
    __syncthreads();   // AF(h1) + WB1(chunk0) + WB0(chunk1) ready

    // ---- layer 2 GEMM: 4 chunks, alternating buffers ----
    gemm_chunk(sm + OFF_AF, 32, 0,  sm + OFF_WB1 + wid * (32 * WBLK), acc, lane);
    __syncthreads();
    stage_w_frags(W2c + 2 * 64 * HID, sm + OFF_WB1, tid);
    gemm_chunk(sm + OFF_AF, 32, 8,  sm + OFF_WB0 + wid * (32 * WBLK), acc, lane);
    __syncthreads();
    stage_w_frags(W2c + 3 * 64 * HID, sm + OFF_WB0, tid);
    gemm_chunk(sm + OFF_AF, 32, 16, sm + OFF_WB1 + wid * (32 * WBLK), acc, lane);
    __syncthreads();
    gemm_chunk(sm + OFF_AF, 32, 24, sm + OFF_WB0 + wid * (32 * WBLK), acc, lane);

    // ---- epilogue 2: d = relu(acc + b2) . w3, reduce, + b3 ----
    {
        const int n0 = wid * 32;
        float p[4][2];
        #pragma unroll
        for (int mt = 0; mt < 4; mt++) { p[mt][0] = 0.f; p[mt][1] = 0.f; }
        #pragma unroll
        for (int mt = 0; mt < 4; mt++)
            #pragma unroll
            for (int nt = 0; nt < 4; nt++)
                #pragma unroll
                for (int reg = 0; reg < 4; reg++) {
                    int col = n0 + nt * 8 + 2 * (lane & 3) + (reg & 1);
                    float f = fmaxf(acc[mt][nt][reg] + sm[OFF_B2 + col], 0.f);
                    p[mt][reg >> 1] += f * sm[OFF_W3 + col];
                }
        // reduce over the 4 lanes sharing a row (lane & 3)
        #pragma unroll
        for (int off = 1; off <= 2; off <<= 1)
            #pragma unroll
            for (int mt = 0; mt < 4; mt++) {
                p[mt][0] += __shfl_xor_sync(0xFFFFFFFFu, p[mt][0], off);
                p[mt][1] += __shfl_xor_sync(0xFFFFFFFFu, p[mt][1], off);
            }
        if ((lane & 3) == 0) {
            #pragma unroll
            for (int mt = 0; mt < 4; mt++)
                #pragma unroll
                for (int h = 0; h < 2; h++) {
                    int row = mt * 16 + (lane >> 2) + 8 * h;
                    sm[OFF_PART + row * 8 + wid] = p[mt][h];
                }
        }
    }
    __syncthreads();
    if (tid < BM) {
        float s = 0.f;
        #pragma unroll
        for (int w = 0; w < 8; w++) s += sm[OFF_PART + tid * 8 + w];
        out[(size_t)(m0 + tid) * NEXP + c] = s + b3[c];
    }
}

extern "C" void kernel_launch(void* const* d_in, const int* in_sizes, int n_in,
                              void* d_out, int out_size)
{
    const float* st = (const float*)d_in[0];
    const float* W1 = (const float*)d_in[1];
    const float* b1 = (const float*)d_in[2];
    const float* W2 = (const float*)d_in[3];
    const float* b2 = (const float*)d_in[4];
    const float* W3 = (const float*)d_in[5];
    const float* b3 = (const float*)d_in[6];
    float* out = (float*)d_out;

    const int smem_bytes = SMEM_FLOATS * (int)sizeof(float);  // 203776
    cudaFuncSetAttribute(moe_disc_mma,
                         cudaFuncAttributeMaxDynamicSharedMemorySize, smem_bytes);
    dim3 grid(65536 / BM, NEXP);
    moe_disc_mma<<<grid, NTHR, smem_bytes>>>(st, W1, b1, W2, b2, W3, b3, out);
}

// round 4
// speedup vs baseline: 7.7725x; 1.7869x over previous
#include <cuda_runtime.h>
#include <cstdint>

#define NEXP   8
#define DIM_S  64
#define HID    256
#define BM     64
#define NTHR   256

// ---- SMEM layout in floats ----
// AF: A-fragments. layer1: [mt4][ks8][lane32][4] (4096 fl)
//                  layer2: [mt4][ks32][lane32][4] (16384 fl)
#define OFF_AF    0
#define OFF_B1    16384
#define OFF_B2    (OFF_B1 + 256)
#define OFF_W3    (OFF_B2 + 256)
#define OFF_PART  (OFF_W3 + 256)          // 64 rows x 8 warps
#define SMEM_FLOATS (OFF_PART + 512)      // 17664 floats = 70656 B

__device__ __forceinline__ uint32_t f2tf32(float f) {
    uint32_t u; asm("cvt.rna.tf32.f32 %0, %1;" : "=r"(u) : "f"(f)); return u;
}
__device__ __forceinline__ float tf32f(float f) {
    return __uint_as_float(f2tf32(f));
}

__device__ __forceinline__ void mma_tf32(float c[4], const uint32_t* a,
                                         uint32_t b0, uint32_t b1) {
    asm volatile(
        "mma.sync.aligned.m16n8k8.row.col.f32.tf32.tf32.f32 "
        "{%0,%1,%2,%3}, {%4,%5,%6,%7}, {%8,%9}, {%0,%1,%2,%3};"
        : "+f"(c[0]), "+f"(c[1]), "+f"(c[2]), "+f"(c[3])
        : "r"(a[0]), "r"(a[1]), "r"(a[2]), "r"(a[3]), "r"(b0), "r"(b1));
}

// GEMM: acc[4][4][4] += A(64 x KS*8, fragments in smem) * B(KS*8 x 32 slice of
// row-major W, LDG'd directly in mma-fragment order).
// m16n8k8 B fragment: lane t holds B[k=(t&3)+4*reg][n = nt*8 + (t>>2)].
template<int TOTKS, int KS>
__device__ __forceinline__ void gemm_ldgB(const float* __restrict__ af,
                                          const float* __restrict__ gW,
                                          int n0, float acc[4][4][4], int lane)
{
    const float* gB = gW + (size_t)(lane & 3) * HID + n0 + (lane >> 2);

    uint32_t breg[3][8];
    uint32_t areg[2][16];

    auto loadB = [&](int ks, uint32_t* b) {
        #pragma unroll
        for (int nt = 0; nt < 4; nt++)
            #pragma unroll
            for (int rg = 0; rg < 2; rg++)
                b[nt * 2 + rg] =
                    f2tf32(__ldg(gB + ((size_t)ks * 8 + rg * 4) * HID + nt * 8));
    };
    auto loadA = [&](int ks, uint32_t* a) {
        #pragma unroll
        for (int mt = 0; mt < 4; mt++) {
            float4 v = *reinterpret_cast<const float4*>(
                af + ((size_t)(mt * TOTKS + ks) * 32 + lane) * 4);
            a[mt * 4 + 0] = __float_as_uint(v.x);
            a[mt * 4 + 1] = __float_as_uint(v.y);
            a[mt * 4 + 2] = __float_as_uint(v.z);
            a[mt * 4 + 3] = __float_as_uint(v.w);
        }
    };

    loadB(0, breg[0]);
    if (KS > 1) loadB(1, breg[1]);
    loadA(0, areg[0]);

    #pragma unroll
    for (int ks = 0; ks < KS; ks++) {
        if (ks + 2 < KS) loadB(ks + 2, breg[(ks + 2) % 3]);
        if (ks + 1 < KS) loadA(ks + 1, areg[(ks + 1) & 1]);
        const uint32_t* a = areg[ks & 1];
        const uint32_t* b = breg[ks % 3];
        #pragma unroll
        for (int nt = 0; nt < 4; nt++)
            #pragma unroll
            for (int mt = 0; mt < 4; mt++)
                mma_tf32(acc[mt][nt], a + mt * 4, b[nt * 2], b[nt * 2 + 1]);
    }
}

__global__ void __launch_bounds__(NTHR, 1)
moe_disc_mma(const float* __restrict__ st,
             const float* __restrict__ W1, const float* __restrict__ b1,
             const float* __restrict__ W2, const float* __restrict__ b2,
             const float* __restrict__ W3, const float* __restrict__ b3,
             float* __restrict__ out)
{
    extern __shared__ float sm[];
    const int tid  = threadIdx.x;
    const int wid  = tid >> 5;
    const int lane = tid & 31;
    const int c    = blockIdx.y;
    const int m0   = blockIdx.x * BM;
    const int n0   = wid * 32;

    const float* W1c = W1 + (size_t)c * DIM_S * HID;
    const float* W2c = W2 + (size_t)c * HID * HID;

    // biases / w3
    sm[OFF_B1 + tid] = b1[c * HID + tid];
    sm[OFF_B2 + tid] = b2[c * HID + tid];
    sm[OFF_W3 + tid] = W3[c * HID + tid];

    // ---- stage layer1 A-fragments (st tile, totks = 8) ----
    #pragma unroll
    for (int i = 0; i < 4; i++) {
        int idx = tid + i * NTHR;        // 0..1023 float4
        int row = idx >> 4;
        int cf  = idx & 15;
        float4 v = *reinterpret_cast<const float4*>(
            st + (size_t)(m0 + row) * DIM_S + cf * 4);
        int mt = row >> 4, r = row & 15;
        float vv[4] = {v.x, v.y, v.z, v.w};
        #pragma unroll
        for (int j = 0; j < 4; j++) {
            int col = cf * 4 + j;
            int ks = col >> 3, kc = col & 7;
            int l2 = (r & 7) * 4 + (kc & 3);
            int r2 = 2 * (kc >> 2) + (r >> 3);
            sm[OFF_AF + ((size_t)(mt * 8 + ks) * 32 + l2) * 4 + r2] = tf32f(vv[j]);
        }
    }
    __syncthreads();

    // ---- layer 1 GEMM (B = W1 via LDG) ----
    float acc[4][4][4];
    #pragma unroll
    for (int a = 0; a < 4; a++)
        #pragma unroll
        for (int b = 0; b < 4; b++)
            #pragma unroll
            for (int d = 0; d < 4; d++) acc[a][b][d] = 0.f;

    gemm_ldgB<8, 8>(sm + OFF_AF, W1c, n0, acc, lane);
    __syncthreads();   // all warps done reading layer1 AF

    // ---- epilogue 1: h1 = tf32(relu(acc + b1)) -> AF (totks = 32) ----
    #pragma unroll
    for (int mt = 0; mt < 4; mt++)
        #pragma unroll
        for (int nt = 0; nt < 4; nt++)
            #pragma unroll
            for (int reg = 0; reg < 4; reg++) {
                int col = n0 + nt * 8 + 2 * (lane & 3) + (reg & 1);
                int row = mt * 16 + (lane >> 2) + 8 * (reg >> 1);
                float f = fmaxf(acc[mt][nt][reg] + sm[OFF_B1 + col], 0.f);
                int ks = col >> 3, kc = col & 7;
                int l2 = (row & 7) * 4 + (kc & 3);
                int r2 = 2 * (kc >> 2) + ((row & 15) >> 3);
                sm[OFF_AF + ((size_t)(mt * 32 + ks) * 32 + l2) * 4 + r2] = tf32f(f);
            }

    // reset acc for layer 2
    #pragma unroll
    for (int a = 0; a < 4; a++)
        #pragma unroll
        for (int b = 0; b < 4; b++)
            #pragma unroll
            for (int d = 0; d < 4; d++) acc[a][b][d] = 0.f;

    __syncthreads();   // h1 fragments visible to all warps

    // ---- layer 2 GEMM (B = W2 via LDG, K=256) ----
    gemm_ldgB<32, 32>(sm + OFF_AF, W2c, n0, acc, lane);

    // ---- epilogue 2: d = relu(acc + b2) . w3, reduce, + b3 ----
    {
        float p[4][2];
        #pragma unroll
        for (int mt = 0; mt < 4; mt++) { p[mt][0] = 0.f; p[mt][1] = 0.f; }
        #pragma unroll
        for (int mt = 0; mt < 4; mt++)
            #pragma unroll
            for (int nt = 0; nt < 4; nt++)
                #pragma unroll
                for (int reg = 0; reg < 4; reg++) {
                    int col = n0 + nt * 8 + 2 * (lane & 3) + (reg & 1);
                    float f = fmaxf(acc[mt][nt][reg] + sm[OFF_B2 + col], 0.f);
                    p[mt][reg >> 1] += f * sm[OFF_W3 + col];
                }
        #pragma unroll
        for (int off = 1; off <= 2; off <<= 1)
            #pragma unroll
            for (int mt = 0; mt < 4; mt++) {
                p[mt][0] += __shfl_xor_sync(0xFFFFFFFFu, p[mt][0], off);
                p[mt][1] += __shfl_xor_sync(0xFFFFFFFFu, p[mt][1], off);
            }
        if ((lane & 3) == 0) {
            #pragma unroll
            for (int mt = 0; mt < 4; mt++)
                #pragma unroll
                for (int h = 0; h < 2; h++) {
                    int row = mt * 16 + (lane >> 2) + 8 * h;
                    sm[OFF_PART + row * 8 + wid] = p[mt][h];
                }
        }
    }
    __syncthreads();
    if (tid < BM) {
        float s = 0.f;
        #pragma unroll
        for (int w = 0; w < 8; w++) s += sm[OFF_PART + tid * 8 + w];
        out[(size_t)(m0 + tid) * NEXP + c] = s + b3[c];
    }
}

extern "C" void kernel_launch(void* const* d_in, const int* in_sizes, int n_in,
                              void* d_out, int out_size)
{
    const float* st = (const float*)d_in[0];
    const float* W1 = (const float*)d_in[1];
    const float* b1 = (const float*)d_in[2];
    const float* W2 = (const float*)d_in[3];
    const float* b2 = (const float*)d_in[4];
    const float* W3 = (const float*)d_in[5];
    const float* b3 = (const float*)d_in[6];
    float* out = (float*)d_out;

    const int smem_bytes = SMEM_FLOATS * (int)sizeof(float);  // 70656
    cudaFuncSetAttribute(moe_disc_mma,
                         cudaFuncAttributeMaxDynamicSharedMemorySize, smem_bytes);
    dim3 grid(65536 / BM, NEXP);
    moe_disc_mma<<<grid, NTHR, smem_bytes>>>(st, W1, b1, W2, b2, W3, b3, out);
}

// round 5
// speedup vs baseline: 8.2666x; 1.0636x over previous
#include <cuda_runtime.h>
#include <cstdint>

#define NEXP   8
#define DIM_S  64
#define HID    256
#define BM     64
#define NTHR   256

// ---- SMEM layout in floats ----
// AF plane layout: word = ((mt*TOTKS + ks)*4 + r2)*32 + lpos
//   lpos = (row&7) | ((((k&3) ^ ks) & 3) << 3)
#define OFF_AF    0
#define OFF_B1    16384
#define OFF_B2    (OFF_B1 + 256)
#define OFF_W3    (OFF_B2 + 256)
#define OFF_PART  (OFF_W3 + 256)          // 64 rows x 8 warps
#define SMEM_FLOATS (OFF_PART + 512)      // 17664 floats = 70656 B

__device__ __forceinline__ uint32_t f2tf32(float f) {
    uint32_t u; asm("cvt.rna.tf32.f32 %0, %1;" : "=r"(u) : "f"(f)); return u;
}
__device__ __forceinline__ float tf32f(float f) {
    return __uint_as_float(f2tf32(f));
}

__device__ __forceinline__ void mma_tf32(float c[4], const uint32_t* a,
                                         uint32_t b0, uint32_t b1) {
    asm volatile(
        "mma.sync.aligned.m16n8k8.row.col.f32.tf32.tf32.f32 "
        "{%0,%1,%2,%3}, {%4,%5,%6,%7}, {%8,%9}, {%0,%1,%2,%3};"
        : "+f"(c[0]), "+f"(c[1]), "+f"(c[2]), "+f"(c[3])
        : "r"(a[0]), "r"(a[1]), "r"(a[2]), "r"(a[3]), "r"(b0), "r"(b1));
}

// GEMM: acc[4][4][4] += A(64 x KS*8, AF plane layout in smem) * B(KS*8 x 32
// slice of row-major W). B columns are permuted: MMA #nt local col q maps to
// phys n = n0 + 4q + nt, so each (ks,rg) B-load is ONE coalesced LDG.128
// (4 rows x 128B). D/A fragment col formulas use the same permutation.
template<int TOTKS, int KS>
__device__ __forceinline__ void gemm_ldgB(const float* __restrict__ af,
                                          const float* __restrict__ gW,
                                          int n0, float acc[4][4][4], int lane)
{
    const float* gB = gW + (size_t)(lane & 3) * HID + n0 + (lane >> 2) * 4;

    uint32_t breg[3][8];   // [ring][nt*2+rg]
    uint32_t areg[2][16];  // [ring][mt*4+r2]

    auto loadB = [&](int ks, uint32_t* b) {
        #pragma unroll
        for (int rg = 0; rg < 2; rg++) {
            float4 v = __ldg(reinterpret_cast<const float4*>(
                gB + (size_t)(ks * 8 + 4 * rg) * HID));
            b[0 * 2 + rg] = f2tf32(v.x);
            b[1 * 2 + rg] = f2tf32(v.y);
            b[2 * 2 + rg] = f2tf32(v.z);
            b[3 * 2 + rg] = f2tf32(v.w);
        }
    };
    auto loadA = [&](int ks, uint32_t* a) {
        const int lpos = (lane >> 2) | ((((lane & 3) ^ ks) & 3) << 3);
        #pragma unroll
        for (int mt = 0; mt < 4; mt++)
            #pragma unroll
            for (int r2 = 0; r2 < 4; r2++)
                a[mt * 4 + r2] = __float_as_uint(
                    af[((size_t)(mt * TOTKS + ks) * 4 + r2) * 32 + lpos]);
    };

    loadB(0, breg[0]);
    if (KS > 1) loadB(1, breg[1]);
    loadA(0, areg[0]);

    #pragma unroll
    for (int ks = 0; ks < KS; ks++) {
        if (ks + 2 < KS) loadB(ks + 2, breg[(ks + 2) % 3]);
        if (ks + 1 < KS) loadA(ks + 1, areg[(ks + 1) & 1]);
        const uint32_t* a = areg[ks & 1];
        const uint32_t* b = breg[ks % 3];
        #pragma unroll
        for (int nt = 0; nt < 4; nt++)
            #pragma unroll
            for (int mt = 0; mt < 4; mt++)
                mma_tf32(acc[mt][nt], a + mt * 4, b[nt * 2], b[nt * 2 + 1]);
    }
}

__global__ void __launch_bounds__(NTHR, 1)
moe_disc_mma(const float* __restrict__ st,
             const float* __restrict__ W1, const float* __restrict__ b1,
             const float* __restrict__ W2, const float* __restrict__ b2,
             const float* __restrict__ W3, const float* __restrict__ b3,
             float* __restrict__ out)
{
    extern __shared__ float sm[];
    const int tid  = threadIdx.x;
    const int wid  = tid >> 5;
    const int lane = tid & 31;
    const int c    = blockIdx.y;
    const int m0   = blockIdx.x * BM;
    const int n0   = wid * 32;

    const float* W1c = W1 + (size_t)c * DIM_S * HID;
    const float* W2c = W2 + (size_t)c * HID * HID;

    sm[OFF_B1 + tid] = b1[c * HID + tid];
    sm[OFF_B2 + tid] = b2[c * HID + tid];
    sm[OFF_W3 + tid] = W3[c * HID + tid];

    // ---- stage layer1 A-fragments (st tile, TOTKS = 8, plane layout) ----
    #pragma unroll
    for (int i = 0; i < 4; i++) {
        int idx = tid + i * NTHR;        // 0..1023 float4
        int row = idx >> 4;
        int cf  = idx & 15;
        float4 v = *reinterpret_cast<const float4*>(
            st + (size_t)(m0 + row) * DIM_S + cf * 4);
        int mt = row >> 4;
        float vv[4] = {v.x, v.y, v.z, v.w};
        #pragma unroll
        for (int j = 0; j < 4; j++) {
            int col = cf * 4 + j;
            int ks  = col >> 3;
            int r2  = 2 * ((col & 7) >> 2) + ((row & 15) >> 3);
            int lp  = (row & 7) | ((((col & 3) ^ ks) & 3) << 3);
            sm[OFF_AF + ((size_t)(mt * 8 + ks) * 4 + r2) * 32 + lp] = tf32f(vv[j]);
        }
    }
    __syncthreads();

    // ---- layer 1 GEMM ----
    float acc[4][4][4];
    #pragma unroll
    for (int a = 0; a < 4; a++)
        #pragma unroll
        for (int b = 0; b < 4; b++)
            #pragma unroll
            for (int d = 0; d < 4; d++) acc[a][b][d] = 0.f;

    gemm_ldgB<8, 8>(sm + OFF_AF, W1c, n0, acc, lane);
    __syncthreads();   // all warps done reading layer1 AF

    // ---- epilogue 1: h1 = tf32(relu(acc + b1)) -> AF (TOTKS = 32) ----
    // phys col of acc[mt][nt][reg] = n0 + 8*(lane&3) + 4*(reg&1) + nt
    {
        float b1v[8];
        #pragma unroll
        for (int j = 0; j < 8; j++)
            b1v[j] = sm[OFF_B1 + n0 + 8 * (lane & 3) + j];
        const int ks2 = (n0 >> 3) + (lane & 3);     // col>>3, const per thread
        #pragma unroll
        for (int mt = 0; mt < 4; mt++)
            #pragma unroll
            for (int nt = 0; nt < 4; nt++)
                #pragma unroll
                for (int reg = 0; reg < 4; reg++) {
                    float f = fmaxf(acc[mt][nt][reg] + b1v[4 * (reg & 1) + nt], 0.f);
                    int r2 = 2 * (reg & 1) + (reg >> 1);
                    int lp = (lane >> 2) | (((nt ^ ks2) & 3) << 3);
                    sm[OFF_AF + ((size_t)(mt * 32 + ks2) * 4 + r2) * 32 + lp] = tf32f(f);
                }
    }

    #pragma unroll
    for (int a = 0; a < 4; a++)
        #pragma unroll
        for (int b = 0; b < 4; b++)
            #pragma unroll
            for (int d = 0; d < 4; d++) acc[a][b][d] = 0.f;

    __syncthreads();   // h1 fragments visible to all warps

    // ---- layer 2 GEMM (K=256) ----
    gemm_ldgB<32, 32>(sm + OFF_AF, W2c, n0, acc, lane);

    // ---- epilogue 2: d = relu(acc + b2) . w3, reduce, + b3 ----
    {
        float b2v[8], w3v[8];
        #pragma unroll
        for (int j = 0; j < 8; j++) {
            b2v[j] = sm[OFF_B2 + n0 + 8 * (lane & 3) + j];
            w3v[j] = sm[OFF_W3 + n0 + 8 * (lane & 3) + j];
        }
        float p[4][2];
        #pragma unroll
        for (int mt = 0; mt < 4; mt++) { p[mt][0] = 0.f; p[mt][1] = 0.f; }
        #pragma unroll
        for (int mt = 0; mt < 4; mt++)
            #pragma unroll
            for (int nt = 0; nt < 4; nt++)
                #pragma unroll
                for (int reg = 0; reg < 4; reg++) {
                    int j = 4 * (reg & 1) + nt;
                    float f = fmaxf(acc[mt][nt][reg] + b2v[j], 0.f);
                    p[mt][reg >> 1] += f * w3v[j];
                }
        #pragma unroll
        for (int off = 1; off <= 2; off <<= 1)
            #pragma unroll
            for (int mt = 0; mt < 4; mt++) {
                p[mt][0] += __shfl_xor_sync(0xFFFFFFFFu, p[mt][0], off);
                p[mt][1] += __shfl_xor_sync(0xFFFFFFFFu, p[mt][1], off);
            }
        if ((lane & 3) == 0) {
            #pragma unroll
            for (int mt = 0; mt < 4; mt++)
                #pragma unroll
                for (int h = 0; h < 2; h++) {
                    int row = mt * 16 + (lane >> 2) + 8 * h;
                    sm[OFF_PART + row * 8 + wid] = p[mt][h];
                }
        }
    }
    __syncthreads();
    if (tid < BM) {
        float s = 0.f;
        #pragma unroll
        for (int w = 0; w < 8; w++) s += sm[OFF_PART + tid * 8 + w];
        out[(size_t)(m0 + tid) * NEXP + c] = s + b3[c];
    }
}

extern "C" void kernel_launch(void* const* d_in, const int* in_sizes, int n_in,
                              void* d_out, int out_size)
{
    const float* st = (const float*)d_in[0];
    const float* W1 = (const float*)d_in[1];
    const float* b1 = (const float*)d_in[2];
    const float* W2 = (const float*)d_in[3];
    const float* b2 = (const float*)d_in[4];
    const float* W3 = (const float*)d_in[5];
    const float* b3 = (const float*)d_in[6];
    float* out = (float*)d_out;

    const int smem_bytes = SMEM_FLOATS * (int)sizeof(float);  // 70656
    cudaFuncSetAttribute(moe_disc_mma,
                         cudaFuncAttributeMaxDynamicSharedMemorySize, smem_bytes);
    dim3 grid(65536 / BM, NEXP);
    moe_disc_mma<<<grid, NTHR, smem_bytes>>>(st, W1, b1, W2, b2, W3, b3, out);
}

// round 6
// speedup vs baseline: 15.5071x; 1.8759x over previous
#include <cuda_runtime.h>
#include <cuda_fp16.h>
#include <cstdint>

#define NEXP   8
#define DIM_S  64
#define HID    256
#define BM     64
#define NTHR   256

// Pre-converted fp16 weights, k-pair packed: u32 = {W[2m][n](lo), W[2m+1][n](hi)}
__device__ uint32_t g_w1p[NEXP * (DIM_S / 2) * HID];   //  65536 u32
__device__ uint32_t g_w2p[NEXP * (HID / 2) * HID];     // 262144 u32

// ---- SMEM (u32 units) ----
// AF: fp16 A-fragment pairs, plane layout:
//   word = ((mt*TOT16 + ks)*4 + reg)*32 + lpos,  reg = h + 2j
//   value = {A[mt*16+8h+rr][16ks+8j+2kq], A[..][..+1]}
//   lpos = rr | (((kq ^ ks) & 3) << 3)
#define OFF_AF    0
#define OFF_B1    8192
#define OFF_B2    8448
#define OFF_W3    8704
#define OFF_PART  8960
#define SMEM_U32  9472          // 37888 bytes

__device__ __forceinline__ uint32_t packh2(float lo, float hi) {
    __half2 h = __floats2half2_rn(lo, hi);
    return *reinterpret_cast<uint32_t*>(&h);
}

__device__ __forceinline__ void mma_f16(float c[4], const uint32_t* a,
                                        uint32_t b0, uint32_t b1) {
    asm volatile(
        "mma.sync.aligned.m16n8k16.row.col.f32.f16.f16.f32 "
        "{%0,%1,%2,%3}, {%4,%5,%6,%7}, {%8,%9}, {%0,%1,%2,%3};"
        : "+f"(c[0]), "+f"(c[1]), "+f"(c[2]), "+f"(c[3])
        : "r"(a[0]), "r"(a[1]), "r"(a[2]), "r"(a[3]), "r"(b0), "r"(b1));
}

// ---- weight convert prologue: fp32 [k][n] -> fp16 k-pair u32 [k/2][n] ----
__global__ void __launch_bounds__(NTHR)
convw(const float* __restrict__ W1, const float* __restrict__ W2)
{
    int i = blockIdx.x * NTHR + threadIdx.x;
    if (i < NEXP * 32 * HID) {
        int c = i >> 13, m = (i >> 8) & 31, n = i & 255;
        const float* b = W1 + ((size_t)c * DIM_S + 2 * m) * HID + n;
        g_w1p[i] = packh2(b[0], b[HID]);
    } else {
        int k = i - NEXP * 32 * HID;
        if (k < NEXP * 128 * HID) {
            int c = k >> 15, m = (k >> 8) & 127, n = k & 255;
            const float* b = W2 + ((size_t)c * HID + 2 * m) * HID + n;
            g_w2p[k] = packh2(b[0], b[HID]);
        }
    }
}

// GEMM: acc[4][4][4] += A(64 x TOT16*16, AF planes) * B(gWp pair-packed,
// this warp's 32 phys cols). n-permutation: MMA #nt local col q ->
// phys n = n0 + 4q + nt (B loads are single LDG.128 per (ks,rg)).
template<int TOT16>
__device__ __forceinline__ void gemm_f16(const uint32_t* __restrict__ af,
                                         const uint32_t* __restrict__ gWp,
                                         int n0, float acc[4][4][4], int lane)
{
    const uint32_t* gB = gWp + (size_t)(lane & 3) * HID + n0 + (lane >> 2) * 4;

    uint32_t breg[3][8];   // [ring][nt*2 + rg]
    uint32_t areg[2][16];  // [ring][mt*4 + reg]

    auto loadB = [&](int ks, uint32_t* b) {
        uint4 v0 = __ldg(reinterpret_cast<const uint4*>(gB + (size_t)(ks * 8) * HID));
        uint4 v1 = __ldg(reinterpret_cast<const uint4*>(gB + (size_t)(ks * 8 + 4) * HID));
        b[0] = v0.x; b[2] = v0.y; b[4] = v0.z; b[6] = v0.w;
        b[1] = v1.x; b[3] = v1.y; b[5] = v1.z; b[7] = v1.w;
    };
    auto loadA = [&](int ks, uint32_t* a) {
        const int lpos = (lane >> 2) | ((((lane & 3) ^ ks) & 3) << 3);
        #pragma unroll
        for (int mt = 0; mt < 4; mt++)
            #pragma unroll
            for (int reg = 0; reg < 4; reg++)
                a[mt * 4 + reg] = af[((size_t)((mt * TOT16 + ks) * 4 + reg)) * 32 + lpos];
    };

    loadB(0, breg[0]);
    if (TOT16 > 1) loadB(1, breg[1]);
    loadA(0, areg[0]);

    #pragma unroll
    for (int ks = 0; ks < TOT16; ks++) {
        if (ks + 2 < TOT16) loadB(ks + 2, breg[(ks + 2) % 3]);
        if (ks + 1 < TOT16) loadA(ks + 1, areg[(ks + 1) & 1]);
        const uint32_t* a = areg[ks & 1];
        const uint32_t* b = breg[ks % 3];
        #pragma unroll
        for (int nt = 0; nt < 4; nt++)
            #pragma unroll
            for (int mt = 0; mt < 4; mt++)
                mma_f16(acc[mt][nt], a + mt * 4, b[nt * 2], b[nt * 2 + 1]);
    }
}

__global__ void __launch_bounds__(NTHR, 2)
moe_disc_mma(const float* __restrict__ st,
             const float* __restrict__ b1, const float* __restrict__ b2,
             const float* __restrict__ W3, const float* __restrict__ b3,
             float* __restrict__ out)
{
    extern __shared__ uint32_t smu[];
    float* smf = reinterpret_cast<float*>(smu);
    const int tid  = threadIdx.x;
    const int wid  = tid >> 5;
    const int lane = tid & 31;
    const int c    = blockIdx.y;
    const int m0   = blockIdx.x * BM;
    const int n0   = wid * 32;

    smf[OFF_B1 + tid] = b1[c * HID + tid];
    smf[OFF_B2 + tid] = b2[c * HID + tid];
    smf[OFF_W3 + tid] = W3[c * HID + tid];

    // ---- stage layer1 A-fragments from st (TOT16 = 4) ----
    #pragma unroll
    for (int i = 0; i < 4; i++) {
        int idx = tid + i * NTHR;        // 0..1023 float4
        int row = idx >> 4;
        int cf  = idx & 15;
        float4 v = *reinterpret_cast<const float4*>(
            st + (size_t)(m0 + row) * DIM_S + cf * 4);
        int mt = row >> 4, h = (row >> 3) & 1, rr = row & 7;
        float lo[2] = {v.x, v.z}, hi[2] = {v.y, v.w};
        #pragma unroll
        for (int pp = 0; pp < 2; pp++) {
            int p  = 2 * cf + pp;        // k-pair index, k = 2p
            int ks = p >> 3, j = (p >> 2) & 1, kq = p & 3;
            int plane = (mt * 4 + ks) * 4 + (h + 2 * j);
            int lpos  = rr | (((kq ^ ks) & 3) << 3);
            smu[OFF_AF + plane * 32 + lpos] = packh2(lo[pp], hi[pp]);
        }
    }
    __syncthreads();

    // ---- layer 1 GEMM ----
    float acc[4][4][4];
    #pragma unroll
    for (int a = 0; a < 4; a++)
        #pragma unroll
        for (int b = 0; b < 4; b++)
            #pragma unroll
            for (int d = 0; d < 4; d++) acc[a][b][d] = 0.f;

    gemm_f16<4>(smu + OFF_AF, g_w1p + (size_t)c * 32 * HID, n0, acc, lane);
    __syncthreads();   // all warps done reading layer1 AF

    // ---- epilogue 1: h1 = fp16(relu(acc + b1)) -> AF (TOT16 = 16) ----
    // phys col of acc[mt][nt][reg] = n0 + 8*(lane&3) + 4*(reg&1) + nt
    {
        float b1v[8];
        #pragma unroll
        for (int j = 0; j < 8; j++)
            b1v[j] = smf[OFF_B1 + n0 + 8 * (lane & 3) + j];
        const int rr = lane >> 2;
        #pragma unroll
        for (int mt = 0; mt < 4; mt++)
            #pragma unroll
            for (int reg = 0; reg < 4; reg++) {
                int h    = reg >> 1;
                int base = n0 + 8 * (lane & 3) + 4 * (reg & 1);
                #pragma unroll
                for (int ps = 0; ps < 2; ps++) {
                    int col0 = base + 2 * ps;
                    float v0 = fmaxf(acc[mt][2 * ps][reg]     + b1v[4 * (reg & 1) + 2 * ps],     0.f);
                    float v1 = fmaxf(acc[mt][2 * ps + 1][reg] + b1v[4 * (reg & 1) + 2 * ps + 1], 0.f);
                    int ks = col0 >> 4, j = (col0 >> 3) & 1, kq = (col0 >> 1) & 3;
                    int plane = (mt * 16 + ks) * 4 + (h + 2 * j);
                    int lpos  = rr | (((kq ^ ks) & 3) << 3);
                    smu[OFF_AF + plane * 32 + lpos] = packh2(v0, v1);
                }
            }
    }

    #pragma unroll
    for (int a = 0; a < 4; a++)
        #pragma unroll
        for (int b = 0; b < 4; b++)
            #pragma unroll
            for (int d = 0; d < 4; d++) acc[a][b][d] = 0.f;

    __syncthreads();   // h1 fragments visible to all warps

    // ---- layer 2 GEMM (K = 256) ----
    gemm_f16<16>(smu + OFF_AF, g_w2p + (size_t)c * 128 * HID, n0, acc, lane);

    // ---- epilogue 2: d = relu(acc + b2) . w3, reduce, + b3 ----
    {
        float b2v[8], w3v[8];
        #pragma unroll
        for (int j = 0; j < 8; j++) {
            b2v[j] = smf[OFF_B2 + n0 + 8 * (lane & 3) + j];
            w3v[j] = smf[OFF_W3 + n0 + 8 * (lane & 3) + j];
        }
        float p[4][2];
        #pragma unroll
        for (int mt = 0; mt < 4; mt++) { p[mt][0] = 0.f; p[mt][1] = 0.f; }
        #pragma unroll
        for (int mt = 0; mt < 4; mt++)
            #pragma unroll
            for (int nt = 0; nt < 4; nt++)
                #pragma unroll
                for (int reg = 0; reg < 4; reg++) {
                    int j = 4 * (reg & 1) + nt;
                    float f = fmaxf(acc[mt][nt][reg] + b2v[j], 0.f);
                    p[mt][reg >> 1] += f * w3v[j];
                }
        #pragma unroll
        for (int off = 1; off <= 2; off <<= 1)
            #pragma unroll
            for (int mt = 0; mt < 4; mt++) {
                p[mt][0] += __shfl_xor_sync(0xFFFFFFFFu, p[mt][0], off);
                p[mt][1] += __shfl_xor_sync(0xFFFFFFFFu, p[mt][1], off);
            }
        if ((lane & 3) == 0) {
            #pragma unroll
            for (int mt = 0; mt < 4; mt++)
                #pragma unroll
                for (int h = 0; h < 2; h++) {
                    int row = mt * 16 + (lane >> 2) + 8 * h;
                    smf[OFF_PART + row * 8 + wid] = p[mt][h];
                }
        }
    }
    __syncthreads();
    if (tid < BM) {
        float s = 0.f;
        #pragma unroll
        for (int w = 0; w < 8; w++) s += smf[OFF_PART + tid * 8 + w];
        out[(size_t)(m0 + tid) * NEXP + c] = s + b3[c];
    }
}

extern "C" void kernel_launch(void* const* d_in, const int* in_sizes, int n_in,
                              void* d_out, int out_size)
{
    const float* st = (const float*)d_in[0];
    const float* W1 = (const float*)d_in[1];
    const float* b1 = (const float*)d_in[2];
    const float* W2 = (const float*)d_in[3];
    const float* b2 = (const float*)d_in[4];
    const float* W3 = (const float*)d_in[5];
    const float* b3 = (const float*)d_in[6];
    float* out = (float*)d_out;

    const int total = NEXP * 32 * HID + NEXP * 128 * HID;  // 327680
    convw<<<(total + NTHR - 1) / NTHR, NTHR>>>(W1, W2);

    const int smem_bytes = SMEM_U32 * 4;   // 37888
    cudaFuncSetAttribute(moe_disc_mma,
                         cudaFuncAttributeMaxDynamicSharedMemorySize, smem_bytes);
    dim3 grid(65536 / BM, NEXP);
    moe_disc_mma<<<grid, NTHR, smem_bytes>>>(st, b1, b2, W3, b3, out);
}

// round 7
// speedup vs baseline: 18.5298x; 1.1949x over previous
#include <cuda_runtime.h>
#include <cuda_fp16.h>
#include <cstdint>

#define NEXP   8
#define DIM_S  64
#define HID    256
#define BM     128
#define NTHR   256

// Pre-shuffled fp16 B-fragment streams (built by convw each launch).
// Layout: [c][wn][ks][quarter q4=rg*2+nthalf][lane][j(=nt within half)] u32
//   u32 = {W[k][n], W[k+1][n]},  k = ks*16 + (lane&3)*2 + 8*rg,
//   n = wn*64 + nt*8 + (lane>>2),  nt = (q4&1)*4 + j
__device__ uint32_t g_w1s[NEXP * 4 * 4 * 512];    //  65536 u32 (256 KB)
__device__ uint32_t g_w2s[NEXP * 4 * 16 * 512];   // 262144 u32 (1 MB)

// ---- SMEM (bytes) ----
// A1: fp16 [128 r][64 k], 128 B/row, chunk swizzle: chunk^= (row&7)
// H1: fp16 [128 r][256 k], 512 B/row, same swizzle (low 3 chunk bits)
#define OFF_A1    0
#define OFF_H1    16384
#define OFF_B1    81920
#define OFF_B2    82944
#define OFF_W3    83968
#define OFF_PART  84992          // [128 rows][4 wn] f32
#define SMEM_BYTES 87040

__device__ __forceinline__ uint32_t packh2(float lo, float hi) {
    __half2 h = __floats2half2_rn(lo, hi);
    return *reinterpret_cast<uint32_t*>(&h);
}
__device__ __forceinline__ uint32_t smem_u32(const void* p) {
    uint32_t a;
    asm("{ .reg .u64 t; cvta.to.shared.u64 t, %1; cvt.u32.u64 %0, t; }" : "=r"(a) : "l"(p));
    return a;
}
__device__ __forceinline__ void mma_f16(float c[4], const uint32_t* a,
                                        uint32_t b0, uint32_t b1) {
    asm volatile(
        "mma.sync.aligned.m16n8k16.row.col.f32.f16.f16.f32 "
        "{%0,%1,%2,%3}, {%4,%5,%6,%7}, {%8,%9}, {%0,%1,%2,%3};"
        : "+f"(c[0]), "+f"(c[1]), "+f"(c[2]), "+f"(c[3])
        : "r"(a[0]), "r"(a[1]), "r"(a[2]), "r"(a[3]), "r"(b0), "r"(b1));
}
__device__ __forceinline__ void ldmx4(uint32_t* a, uint32_t addr) {
    asm volatile("ldmatrix.sync.aligned.m8n8.x4.shared.b16 {%0,%1,%2,%3}, [%4];"
        : "=r"(a[0]), "=r"(a[1]), "=r"(a[2]), "=r"(a[3]) : "r"(addr));
}

// ---- prologue: build B-fragment streams from fp32 row-major weights ----
__global__ void __launch_bounds__(NTHR)
convw(const float* __restrict__ W1, const float* __restrict__ W2)
{
    int i = blockIdx.x * NTHR + threadIdx.x;
    if (i < NEXP * 4 * 4 * 512) {            // W1 stream
        int j = i & 3, lane = (i >> 2) & 31, q4 = (i >> 7) & 3;
        int ks = (i >> 9) & 3, w = (i >> 11) & 3, c = i >> 13;
        int rg = q4 >> 1, nt = (q4 & 1) * 4 + j;
        int n = w * 64 + nt * 8 + (lane >> 2);
        int k = ks * 16 + (lane & 3) * 2 + rg * 8;
        const float* p = W1 + ((size_t)c * DIM_S + k) * HID + n;
        g_w1s[i] = packh2(p[0], p[HID]);
    } else {
        i -= NEXP * 4 * 4 * 512;
        if (i < NEXP * 4 * 16 * 512) {       // W2 stream
            int j = i & 3, lane = (i >> 2) & 31, q4 = (i >> 7) & 3;
            int ks = (i >> 9) & 15, w = (i >> 13) & 3, c = i >> 15;
            int rg = q4 >> 1, nt = (q4 & 1) * 4 + j;
            int n = w * 64 + nt * 8 + (lane >> 2);
            int k = ks * 16 + (lane & 3) * 2 + rg * 8;
            const float* p = W2 + ((size_t)c * HID + k) * HID + n;
            g_w2s[i] = packh2(p[0], p[HID]);
        }
    }
}

// GEMM: acc[4][8][4] += A(rows wm*64..+63, K = TOT16*16, smem swizzled
// row-major fp16, ROWB bytes/row) * B(fragment stream, this warp's 64 cols).
template<int TOT16, int ROWB>
__device__ __forceinline__ void gemm(const uint32_t* __restrict__ bs,
                                     uint32_t afb, float acc[4][8][4],
                                     int lane, int wm64)
{
    const int arow = wm64 + ((lane >> 3) & 1) * 8 + (lane & 7);
    const int jj   = lane >> 4;
    const uint32_t abase = afb + arow * ROWB;
    const int      amask = arow & 7;

    uint32_t breg[2][16];   // [ring][nt*2+rg]
    uint32_t areg[2][4];

    auto loadB = [&](int ks, uint32_t* b) {
        const uint4* p = reinterpret_cast<const uint4*>(
            bs + (size_t)ks * 512 + lane * 4);
        uint4 v0 = __ldg(p);        // rg0, nt0-3
        uint4 v1 = __ldg(p + 32);   // rg0, nt4-7
        uint4 v2 = __ldg(p + 64);   // rg1, nt0-3
        uint4 v3 = __ldg(p + 96);   // rg1, nt4-7
        b[0]  = v0.x; b[2]  = v0.y; b[4]  = v0.z; b[6]  = v0.w;
        b[8]  = v1.x; b[10] = v1.y; b[12] = v1.z; b[14] = v1.w;
        b[1]  = v2.x; b[3]  = v2.y; b[5]  = v2.z; b[7]  = v2.w;
        b[9]  = v3.x; b[11] = v3.y; b[13] = v3.z; b[15] = v3.w;
    };
    auto loadA = [&](int ks, int mt, uint32_t* a) {
        int chunk = (2 * ks + jj) ^ amask;
        ldmx4(a, abase + mt * 16 * ROWB + chunk * 16);
    };

    loadB(0, breg[0]);
    loadA(0, 0, areg[0]);

    #pragma unroll
    for (int ks = 0; ks < TOT16; ks++) {
        if (ks + 1 < TOT16) loadB(ks + 1, breg[(ks + 1) & 1]);
        const uint32_t* b = breg[ks & 1];
        #pragma unroll
        for (int mt = 0; mt < 4; mt++) {
            if (!(mt == 3 && ks + 1 == TOT16))
                loadA(mt == 3 ? ks + 1 : ks, (mt + 1) & 3, areg[(mt + 1) & 1]);
            const uint32_t* a = areg[mt & 1];
            #pragma unroll
            for (int nt = 0; nt < 8; nt++)
                mma_f16(acc[mt][nt], a, b[nt * 2], b[nt * 2 + 1]);
        }
    }
}

__global__ void __launch_bounds__(NTHR, 1)
moe_disc_mma(const float* __restrict__ st,
             const float* __restrict__ b1, const float* __restrict__ b2,
             const float* __restrict__ W3, const float* __restrict__ b3,
             float* __restrict__ out)
{
    extern __shared__ char smem[];
    float* smf = reinterpret_cast<float*>(smem);
    const uint32_t sb = smem_u32(smem);
    const int tid  = threadIdx.x;
    const int wid  = tid >> 5;
    const int lane = tid & 31;
    const int wm   = wid >> 2;        // 0..1 : row half
    const int wn   = wid & 3;         // 0..3 : 64-col block
    const int wm64 = wm * 64;
    const int c    = blockIdx.y;
    const int m0   = blockIdx.x * BM;

    // ---- stage biases / w3 ----
    smf[(OFF_B1 >> 2) + tid] = b1[c * HID + tid];
    smf[(OFF_B2 >> 2) + tid] = b2[c * HID + tid];
    smf[(OFF_W3 >> 2) + tid] = W3[c * HID + tid];

    // ---- stage A1 = fp16(st tile) [128 x 64], swizzled row-major ----
    #pragma unroll
    for (int i = 0; i < 8; i++) {
        int idx = tid + i * NTHR;       // 0..2047 float4
        int row = idx >> 4, f4 = idx & 15;
        float4 v = *reinterpret_cast<const float4*>(
            st + (size_t)(m0 + row) * DIM_S + f4 * 4);
        uint32_t byte = OFF_A1 + row * 128
                      + (uint32_t)(((f4 >> 1) ^ (row & 7)) * 16 + 8 * (f4 & 1));
        *reinterpret_cast<uint2*>(smem + byte) =
            make_uint2(packh2(v.x, v.y), packh2(v.z, v.w));
    }
    __syncthreads();

    float acc[4][8][4];
    #pragma unroll
    for (int a = 0; a < 4; a++)
        #pragma unroll
        for (int b = 0; b < 8; b++)
            #pragma unroll
            for (int e = 0; e < 4; e++) acc[a][b][e] = 0.f;

    // ---- layer 1 GEMM (K = 64) ----
    gemm<4, 128>(g_w1s + ((size_t)(c * 4 + wn)) * 2048, sb + OFF_A1,
                 acc, lane, wm64);

    // ---- epilogue 1: H1 = fp16(relu(acc + b1)), swizzled row-major ----
    {
        float b1v[16];
        #pragma unroll
        for (int nt = 0; nt < 8; nt++) {
            int k0 = wn * 64 + nt * 8 + 2 * (lane & 3);
            b1v[nt * 2]     = smf[(OFF_B1 >> 2) + k0];
            b1v[nt * 2 + 1] = smf[(OFF_B1 >> 2) + k0 + 1];
        }
        #pragma unroll
        for (int mt = 0; mt < 4; mt++)
            #pragma unroll
            for (int nt = 0; nt < 8; nt++) {
                int r0 = wm64 + mt * 16 + (lane >> 2);
                int chunk = wn * 8 + nt;
                uint32_t p0 = packh2(
                    fmaxf(acc[mt][nt][0] + b1v[nt * 2], 0.f),
                    fmaxf(acc[mt][nt][1] + b1v[nt * 2 + 1], 0.f));
                uint32_t p1 = packh2(
                    fmaxf(acc[mt][nt][2] + b1v[nt * 2], 0.f),
                    fmaxf(acc[mt][nt][3] + b1v[nt * 2 + 1], 0.f));
                uint32_t by0 = OFF_H1 + r0 * 512
                             + ((chunk ^ (r0 & 7)) * 16) + 4 * (lane & 3);
                int r1 = r0 + 8;
                uint32_t by1 = OFF_H1 + r1 * 512
                             + ((chunk ^ (r1 & 7)) * 16) + 4 * (lane & 3);
                *reinterpret_cast<uint32_t*>(smem + by0) = p0;
                *reinterpret_cast<uint32_t*>(smem + by1) = p1;
            }
    }
    #pragma unroll
    for (int a = 0; a < 4; a++)
        #pragma unroll
        for (int b = 0; b < 8; b++)
            #pragma unroll
            for (int e = 0; e < 4; e++) acc[a][b][e] = 0.f;

    __syncthreads();   // H1 visible to all warps

    // ---- layer 2 GEMM (K = 256) ----
    gemm<16, 512>(g_w2s + ((size_t)(c * 4 + wn)) * 8192, sb + OFF_H1,
                  acc, lane, wm64);

    // ---- epilogue 2: d = relu(acc + b2) . w3, reduce, + b3 ----
    {
        float b2v[16], w3v[16];
        #pragma unroll
        for (int nt = 0; nt < 8; nt++) {
            int k0 = wn * 64 + nt * 8 + 2 * (lane & 3);
            b2v[nt * 2]     = smf[(OFF_B2 >> 2) + k0];
            b2v[nt * 2 + 1] = smf[(OFF_B2 >> 2) + k0 + 1];
            w3v[nt * 2]     = smf[(OFF_W3 >> 2) + k0];
            w3v[nt * 2 + 1] = smf[(OFF_W3 >> 2) + k0 + 1];
        }
        float p[4][2];
        #pragma unroll
        for (int mt = 0; mt < 4; mt++) { p[mt][0] = 0.f; p[mt][1] = 0.f; }
        #pragma unroll
        for (int mt = 0; mt < 4; mt++)
            #pragma unroll
            for (int nt = 0; nt < 8; nt++) {
                p[mt][0] += fmaxf(acc[mt][nt][0] + b2v[nt * 2], 0.f)     * w3v[nt * 2]
                          + fmaxf(acc[mt][nt][1] + b2v[nt * 2 + 1], 0.f) * w3v[nt * 2 + 1];
                p[mt][1] += fmaxf(acc[mt][nt][2] + b2v[nt * 2], 0.f)     * w3v[nt * 2]
                          + fmaxf(acc[mt][nt][3] + b2v[nt * 2 + 1], 0.f) * w3v[nt * 2 + 1];
            }
        #pragma unroll
        for (int off = 1; off <= 2; off <<= 1)
            #pragma unroll
            for (int mt = 0; mt < 4; mt++) {
                p[mt][0] += __shfl_xor_sync(0xFFFFFFFFu, p[mt][0], off);
                p[mt][1] += __shfl_xor_sync(0xFFFFFFFFu, p[mt][1], off);
            }
        if ((lane & 3) == 0) {
            #pragma unroll
            for (int mt = 0; mt < 4; mt++)
                #pragma unroll
                for (int h = 0; h < 2; h++) {
                    int row = wm64 + mt * 16 + (lane >> 2) + 8 * h;
                    smf[(OFF_PART >> 2) + row * 4 + wn] = p[mt][h];
                }
        }
    }
    __syncthreads();
    if (tid < BM) {
        const float* q = smf + (OFF_PART >> 2) + tid * 4;
        out[(size_t)(m0 + tid) * NEXP + c] = q[0] + q[1] + q[2] + q[3] + b3[c];
    }
}

extern "C" void kernel_launch(void* const* d_in, const int* in_sizes, int n_in,
                              void* d_out, int out_size)
{
    const float* st = (const float*)d_in[0];
    const float* W1 = (const float*)d_in[1];
    const float* b1 = (const float*)d_in[2];
    const float* W2 = (const float*)d_in[3];
    const float* b2 = (const float*)d_in[4];
    const float* W3 = (const float*)d_in[5];
    const float* b3 = (const float*)d_in[6];
    float* out = (float*)d_out;

    const int total = NEXP * 4 * 4 * 512 + NEXP * 4 * 16 * 512;  // 327680
    convw<<<(total + NTHR - 1) / NTHR, NTHR>>>(W1, W2);

    cudaFuncSetAttribute(moe_disc_mma,
                         cudaFuncAttributeMaxDynamicSharedMemorySize, SMEM_BYTES);
    dim3 grid(65536 / BM, NEXP);
    moe_disc_mma<<<grid, NTHR, SMEM_BYTES>>>(st, b1, b2, W3, b3, out);
}